// round 15
// baseline (speedup 1.0000x reference)
#include <cuda_runtime.h>
#include <cuda_bf16.h>
#include <math.h>
#include <stdint.h>

// ---------------- problem constants ----------------
#define Bsz   16384
#define Wsz   5
#define Lsz   20
#define Esz   50
#define Vsz   100000
#define Csz   128
#define Hsz   4096
#define Osz   50
#define NW    (Bsz*Wsz)
#define KP2   256          // padded K (W*E = 250 -> 256)
// chunked hi/lo layout: sample = 8 chunks; chunk q = [hi k=32q..32q+31 | lo same] (64 bf16 = 128B)
#define SSTR  512          // bf16 elems per sample (256 hi + 256 lo)

// ---------------- device scratch ----------------
__device__ float d_proj[3 * Csz * Esz];
__device__ __align__(16) __nv_bfloat16 d_g1[Bsz * SSTR];      // 16.8 MB A hi/lo chunked
__device__ __align__(16) __nv_bfloat16 d_w1i[Hsz * SSTR];     // 4 MB   B hi/lo chunked
__device__ __align__(16) __nv_bfloat16 d_w2h[64 * Hsz];       // 512 KB
__device__ __align__(16) __nv_bfloat16 d_w2l[64 * Hsz];       // 512 KB
__device__ float d_b2p[64];
__device__ float d_logits[Bsz * 64];                          // 4 MB

// ---------------- helpers ----------------
__device__ __forceinline__ uint32_t smem_u32(const void* p) {
    uint32_t a;
    asm("{ .reg .u64 t; cvta.to.shared.u64 t, %1; cvt.u32.u64 %0, t; }" : "=r"(a) : "l"(p));
    return a;
}
#define SWZ128(o) ((o) ^ ((((uint32_t)(o)) >> 3) & 0x70))
__device__ __forceinline__ void cp16(uint32_t saddr, const void* g) {
    asm volatile("cp.async.cg.shared.global [%0], [%1], 16;" :: "r"(saddr), "l"(g));
}
#define CP_COMMIT() asm volatile("cp.async.commit_group;" ::: "memory")
#define CP_WAIT(n)  asm volatile("cp.async.wait_group %0;" :: "n"(n) : "memory")

__device__ __forceinline__ void ldm_x4(uint32_t* r, uint32_t saddr) {
    asm volatile("ldmatrix.sync.aligned.m8n8.x4.shared.b16 {%0,%1,%2,%3}, [%4];"
                 : "=r"(r[0]), "=r"(r[1]), "=r"(r[2]), "=r"(r[3]) : "r"(saddr));
}
__device__ __forceinline__ void mma16816(float* c, const uint32_t* a, uint32_t b0, uint32_t b1) {
    asm volatile("mma.sync.aligned.m16n8k16.row.col.f32.bf16.bf16.f32 "
                 "{%0,%1,%2,%3}, {%4,%5,%6,%7}, {%8,%9}, {%0,%1,%2,%3};"
                 : "+f"(c[0]), "+f"(c[1]), "+f"(c[2]), "+f"(c[3])
                 : "r"(a[0]), "r"(a[1]), "r"(a[2]), "r"(a[3]), "r"(b0), "r"(b1));
}

// ---------------- kernel 1: fused prep (zero logits, proj tables, w1 chunked, w2 split)
__global__ __launch_bounds__(256) void k_prep(const float* __restrict__ conv_w,
                                              const float* __restrict__ char_emb,
                                              const float* __restrict__ w1,
                                              const float* __restrict__ w2,
                                              const float* __restrict__ b2) {
    int blk = blockIdx.x;
    int tid = threadIdx.x;
    if (blk < 1024) {
        ((float4*)d_logits)[blk * 256 + tid] = make_float4(0.f, 0.f, 0.f, 0.f);
    } else if (blk < 1152) {
        if (tid >= 150) return;
        int k = tid / 50, e = tid % 50;
        int c = blk - 1024;
        float acc = 0.f;
#pragma unroll
        for (int i = 0; i < Esz; ++i)
            acc += conv_w[(e * Esz + i) * 3 + k] * char_emb[c * Esz + i];
        d_proj[k * (Csz * Esz) + c * Esz + e] = acc;
    } else if (blk < 5248) {
        int idx = (blk - 1152) * 256 + tid;            // < 4096*256
        int n = idx >> 8, k = idx & 255;
        float v = (k < 250) ? w1[n * 250 + k] : 0.f;
        __nv_bfloat16 hi = __float2bfloat16(v);
        __nv_bfloat16 lo = __float2bfloat16(v - __bfloat162float(hi));
        int q = k >> 5, p = k & 31;
        d_w1i[n * SSTR + q * 64 + p]      = hi;
        d_w1i[n * SSTR + q * 64 + 32 + p] = lo;
    } else {
        int idx = (blk - 5248) * 256 + tid;            // < 64*4096
        int o = idx >> 12;
        float v = (o < 50) ? w2[o * Hsz + (idx & 4095)] : 0.f;
        __nv_bfloat16 hi = __float2bfloat16(v);
        __nv_bfloat16 lo = __float2bfloat16(v - __bfloat162float(hi));
        d_w2h[idx] = hi;
        d_w2l[idx] = lo;
        if (idx < 64) d_b2p[idx] = (idx < 50) ? b2[idx] : 0.f;
    }
}

// ---------------- no-op spacer so k_fc1f lands in the ncu capture slot -------
__global__ void k_noop() {
    if (threadIdx.x > 1024) d_b2p[0] = 0.f;   // never true
}

// ---------------- kernel 3: features (warp-per-word, prefetched) -------------
__global__ __launch_bounds__(512) void k_feat(const int* __restrict__ x, const int* __restrict__ w2c,
                                              const float* __restrict__ wemb, const float* __restrict__ convb) {
    extern __shared__ float smf[];
    float* sp  = smf;            // 19200 floats: proj tables
    float* scb = smf + 19200;    // 64: conv bias

    int tid = threadIdx.x;
    for (int i = tid; i < 4800; i += 512)
        ((float4*)sp)[i] = ((const float4*)d_proj)[i];
    if (tid < 50) scb[tid] = convb[tid];
    __syncthreads();

    int lane = tid & 31, warp = tid >> 5;
    int base = blockIdx.x * 64 + warp * 4;
    bool act = lane < 25;
    int e2 = lane << 1;
    float2 cb = act ? *(const float2*)(scb + e2) : make_float2(0.f, 0.f);

    int xvs[4];
#pragma unroll
    for (int it = 0; it < 4; ++it) xvs[it] = x[base + it];
    int cidn = (lane < Lsz) ? w2c[xvs[0] * Lsz + lane] : 0;

#pragma unroll
    for (int it = 0; it < 4; ++it) {
        int xv = xvs[it];
        int cidreg = cidn;
        if (it < 3) cidn = (lane < Lsz) ? w2c[xvs[it + 1] * Lsz + lane] : 0;  // prefetch next
        float2 we = act ? *(const float2*)(wemb + xv * 50 + e2)              // early issue
                        : make_float2(0.f, 0.f);

        float m0 = -1e30f, m1 = -1e30f;
        int cp = 0;
        int cc = __shfl_sync(0xffffffffu, cidreg, 0);
#pragma unroll
        for (int l = 0; l < Lsz; ++l) {
            int cn = (l < Lsz - 1) ? __shfl_sync(0xffffffffu, cidreg, l + 1) : 0;
            if (act) {
                float2 s0 = *(const float2*)(sp + cp * 50 + e2);
                float2 s1 = *(const float2*)(sp + 6400 + cc * 50 + e2);
                float2 s2 = *(const float2*)(sp + 12800 + cn * 50 + e2);
                m0 = fmaxf(m0, s0.x + s1.x + s2.x);
                m1 = fmaxf(m1, s0.y + s1.y + s2.y);
            }
            cp = cc; cc = cn;
        }

        int b = (base + it) / Wsz, w = (base + it) - b * Wsz;
        if (act) {
            float v0 = we.x + m0 + cb.x;
            float v1 = we.y + m1 + cb.y;
            __nv_bfloat16 h0 = __float2bfloat16(v0);
            __nv_bfloat16 h1 = __float2bfloat16(v1);
            __nv_bfloat162 vh; vh.x = h0; vh.y = h1;
            __nv_bfloat162 vl;
            vl.x = __float2bfloat16(v0 - __bfloat162float(h0));
            vl.y = __float2bfloat16(v1 - __bfloat162float(h1));
            int col = w * 50 + e2;                       // even, pair stays in chunk
            int q = col >> 5, p = col & 31;
            int off = b * SSTR + q * 64 + p;
            *(__nv_bfloat162*)(d_g1 + off)      = vh;
            *(__nv_bfloat162*)(d_g1 + off + 32) = vl;
        } else if (lane < 28 && w == 0) {                // zero pads cols [250,256)
            int col = 250 + ((lane - 25) << 1);          // 250, 252, 254 (chunk 7)
            int q = col >> 5, p = col & 31;
            int off = b * SSTR + q * 64 + p;
            __nv_bfloat162 z2; z2.x = __float2bfloat16(0.f); z2.y = z2.x;
            *(__nv_bfloat162*)(d_g1 + off)      = z2;
            *(__nv_bfloat162*)(d_g1 + off + 32) = z2;
        }
    }
}

// ---------------- kernel 4: fused fc1 + fc2-partial, CTA 128x128 -------------
// 3-term split GEMM acc = Ah*Bh + Ah*Bl + Al*Bh. K=256 in 8 slabs of 32;
// smem row (128B) = [hi 32 bf16 | lo 32 bf16]. 8 warps = 2(M)x4(N), warp 64x32.
// __launch_bounds__(256,2): 2 CTAs/SM. Slab loop ordering (safe + early):
//   CP_WAIT(1) -> __syncthreads -> stage(s+2) -> compute(s)
// The barrier proves all compute(s-1) readers of buffer (s+2)%3 finished
// BEFORE the new cp.async writes are issued; stage leads its consumer by
// ~1.5 slabs of compute. k-step smem offsets hoisted out of the slab loop.
#define FC1_SMEM 98304
__global__ __launch_bounds__(256, 2) void k_fc1f(const float* __restrict__ b1) {
    extern __shared__ __align__(1024) char smc[];
    uint32_t sbase = smem_u32(smc);
    int tid = threadIdx.x;
    int lane = tid & 31, warp = tid >> 5;
    int wm = warp & 1, wn = warp >> 1;
    int bm = blockIdx.y << 7, bn = blockIdx.x << 7;

    float acc[4][4][4];
#pragma unroll
    for (int i = 0; i < 4; ++i)
#pragma unroll
        for (int j = 0; j < 4; ++j)
#pragma unroll
            for (int q = 0; q < 4; ++q) acc[i][j][q] = 0.f;

    const char* gA = (const char*)d_g1;
    const char* gB = (const char*)d_w1i;

    int lrow  = (lane & 7) + ((lane >> 3) & 1) * 8;
    int lchnk = (lane >> 4) << 4;
    uint32_t lsw = (uint32_t)((lane & 7) << 4);

    // slab-invariant k-step offsets (hoisted)
    uint32_t khiK[2], kloK[2];
#pragma unroll
    for (int kb = 0; kb < 2; ++kb) {
        khiK[kb] = (uint32_t)(kb * 32 + lchnk) ^ lsw;
        kloK[kb] = (uint32_t)(64 + kb * 32 + lchnk) ^ lsw;
    }

    // stage slab s (chunk s = 128 bytes per sample row) into buffer buf
    auto stage = [&](int s, int buf) {
        uint32_t ab = sbase + buf * 32768;
        uint32_t bb = ab + 16384;
        int koff = s * 128;
#pragma unroll
        for (int i = 0; i < 4; ++i) {
            int idx = tid + (i << 8);
            int r = idx >> 3, c = (idx & 7) << 4;
            cp16(ab + SWZ128(r * 128 + c), gA + (size_t)(bm + r) * 1024 + koff + c);
        }
#pragma unroll
        for (int i = 0; i < 4; ++i) {
            int idx = tid + (i << 8);
            int r = idx >> 3, c = (idx & 7) << 4;
            cp16(bb + SWZ128(r * 128 + c), gB + (size_t)(bn + r) * 1024 + koff + c);
        }
    };

    // w2 epilogue slice (64 x 128 cols, hi+lo) -> [64K, 96K)
    auto stage_w2 = [&]() {
        const char* gW2h = (const char*)d_w2h;
        const char* gW2l = (const char*)d_w2l;
#pragma unroll
        for (int i = 0; i < 8; ++i) {
            int idx = tid + (i << 8);
            int hl = idx >> 10, rem = idx & 1023;
            int j = rem >> 9, rem2 = rem & 511;
            int o = rem2 >> 3, c = (rem2 & 7) << 4;
            const char* src = (hl ? gW2l : gW2h) + (size_t)o * 8192 + (size_t)(bn + (j << 6)) * 2 + c;
            cp16(sbase + 65536 + hl * 16384 + (j << 13) + SWZ128(o * 128 + c), src);
        }
    };

    stage(0, 0); CP_COMMIT();
    stage(1, 1); CP_COMMIT();

    for (int s = 0; s < 8; ++s) {
        int buf = s - (s / 3) * 3;                       // s % 3
        CP_WAIT(1);                                      // slab s landed (FIFO retire)
        __syncthreads();                                 // all compute(s-1) readers done

        // stage ahead BEFORE compute: safe (barrier above) and early (~1.5 slabs lead)
        if (s + 2 < 8) {
            int nb = (s + 2) - ((s + 2) / 3) * 3;
            stage(s + 2, nb); CP_COMMIT();
        } else if (s == 6) {
            stage_w2(); CP_COMMIT();                     // buf-2 region free after compute(5)
        }

        uint32_t ab = sbase + buf * 32768;
        uint32_t bb = ab + 16384;
        uint32_t arow[4], brow[2];
#pragma unroll
        for (int mt = 0; mt < 4; ++mt)
            arow[mt] = ab + (uint32_t)((wm << 6) + (mt << 4) + lrow) * 128;
#pragma unroll
        for (int np = 0; np < 2; ++np)
            brow[np] = bb + (uint32_t)((wn << 5) + (np << 4) + lrow) * 128;

#pragma unroll
        for (int kb = 0; kb < 2; ++kb) {                 // 2 k-steps of 16
            uint32_t khi = khiK[kb], klo = kloK[kb];

            // pass 1: ah·bh
            uint32_t ah[4][4], bh[2][4];
#pragma unroll
            for (int np = 0; np < 2; ++np) ldm_x4(bh[np], brow[np] + khi);
#pragma unroll
            for (int mt = 0; mt < 4; ++mt) ldm_x4(ah[mt], arow[mt] + khi);
#pragma unroll
            for (int mt = 0; mt < 4; ++mt)
#pragma unroll
                for (int np = 0; np < 2; ++np) {
                    mma16816(acc[mt][np * 2],     ah[mt], bh[np][0], bh[np][2]);
                    mma16816(acc[mt][np * 2 + 1], ah[mt], bh[np][1], bh[np][3]);
                }

            // pass 2: ah·bl
            uint32_t bl[2][4];
#pragma unroll
            for (int np = 0; np < 2; ++np) ldm_x4(bl[np], brow[np] + klo);
#pragma unroll
            for (int mt = 0; mt < 4; ++mt)
#pragma unroll
                for (int np = 0; np < 2; ++np) {
                    mma16816(acc[mt][np * 2],     ah[mt], bl[np][0], bl[np][2]);
                    mma16816(acc[mt][np * 2 + 1], ah[mt], bl[np][1], bl[np][3]);
                }

            // pass 3: al·bh (bh kept live)
            uint32_t al[4][4];
#pragma unroll
            for (int mt = 0; mt < 4; ++mt) ldm_x4(al[mt], arow[mt] + klo);
#pragma unroll
            for (int mt = 0; mt < 4; ++mt)
#pragma unroll
                for (int np = 0; np < 2; ++np) {
                    mma16816(acc[mt][np * 2],     al[mt], bh[np][0], bh[np][2]);
                    mma16816(acc[mt][np * 2 + 1], al[mt], bh[np][1], bh[np][3]);
                }
        }
    }
    __syncthreads();   // all compute(7) reads done before h-store reuses bufs 0/1

    // ---- epilogue phase 2: tanh + split, h tile -> smem [0, 64K) ----
    int r0 = lane >> 2, c0 = (lane & 3) << 1;
#pragma unroll
    for (int mt = 0; mt < 4; ++mt) {
#pragma unroll
        for (int nt = 0; nt < 4; ++nt) {
            int col = (wn << 5) + (nt << 3) + c0;       // 0..127 local
            float bias0 = b1[bn + col], bias1 = b1[bn + col + 1];
            int slab = col >> 6, inner = col & 63;
#pragma unroll
            for (int half = 0; half < 2; ++half) {
                int rowl = (wm << 6) + (mt << 4) + r0 + (half << 3);
                float t0 = tanhf(acc[mt][nt][half * 2 + 0] + bias0);
                float t1 = tanhf(acc[mt][nt][half * 2 + 1] + bias1);
                __nv_bfloat16 h0 = __float2bfloat16(t0);
                __nv_bfloat16 h1 = __float2bfloat16(t1);
                __nv_bfloat162 vh; vh.x = h0; vh.y = h1;
                __nv_bfloat162 vl;
                vl.x = __float2bfloat16(t0 - __bfloat162float(h0));
                vl.y = __float2bfloat16(t1 - __bfloat162float(h1));
                uint32_t off = SWZ128((uint32_t)rowl * 128 + inner * 2);
                *(__nv_bfloat162*)(smc + (slab << 14) + off)         = vh;
                *(__nv_bfloat162*)(smc + 32768 + (slab << 14) + off) = vl;
            }
        }
    }
    CP_WAIT(0);
    __syncthreads();

    // ---- epilogue phase 3: mini GEMM, logits partial [128x64], K=128 ----
    float a2[4][2][4];
#pragma unroll
    for (int i = 0; i < 4; ++i)
#pragma unroll
        for (int j = 0; j < 2; ++j)
#pragma unroll
            for (int q = 0; q < 4; ++q) a2[i][j][q] = 0.f;

#pragma unroll
    for (int slab = 0; slab < 2; ++slab) {
        uint32_t ahb = sbase + (slab << 14);
        uint32_t alb = ahb + 32768;
        uint32_t bhb = sbase + 65536 + (slab << 13);
        uint32_t blb = bhb + 16384;
        uint32_t brw = (uint32_t)((wn << 4) + lrow) * 128;
#pragma unroll
        for (int kb = 0; kb < 4; ++kb) {
            uint32_t koffb = (uint32_t)(kb * 32 + lchnk) ^ lsw;
            uint32_t bh[4], bl[4];
            ldm_x4(bh, bhb + brw + koffb);
            ldm_x4(bl, blb + brw + koffb);
#pragma unroll
            for (int mt = 0; mt < 4; ++mt) {
                uint32_t arw = (uint32_t)((wm << 6) + (mt << 4) + lrow) * 128;
                uint32_t ah[4], al[4];
                ldm_x4(ah, ahb + arw + koffb);
                ldm_x4(al, alb + arw + koffb);
                mma16816(a2[mt][0], ah, bh[0], bh[2]);
                mma16816(a2[mt][1], ah, bh[1], bh[3]);
                mma16816(a2[mt][0], ah, bl[0], bl[2]);
                mma16816(a2[mt][1], ah, bl[1], bl[3]);
                mma16816(a2[mt][0], al, bh[0], bh[2]);
                mma16816(a2[mt][1], al, bh[1], bh[3]);
            }
        }
    }

    // ---- epilogue phase 4: atomic accumulate ----
#pragma unroll
    for (int mt = 0; mt < 4; ++mt) {
#pragma unroll
        for (int nt = 0; nt < 2; ++nt) {
            int colg = (wn << 4) + (nt << 3) + c0;
#pragma unroll
            for (int half = 0; half < 2; ++half) {
                int rowg = bm + (wm << 6) + (mt << 4) + r0 + (half << 3);
                atomicAdd(&d_logits[rowg * 64 + colg],     a2[mt][nt][half * 2 + 0]);
                atomicAdd(&d_logits[rowg * 64 + colg + 1], a2[mt][nt][half * 2 + 1]);
            }
        }
    }
}

// ---------------- kernel 5: softmax over logits (vectorized loads) ----------
__global__ __launch_bounds__(256) void k_smax(float* __restrict__ out) {
    int r = blockIdx.x * 256 + threadIdx.x;
    const float4* lr4 = (const float4*)(d_logits + r * 64);
    float v[52];
#pragma unroll
    for (int c4 = 0; c4 < 13; ++c4) {                    // 52 >= 50 cols
        float4 t = lr4[c4];
        v[c4 * 4 + 0] = t.x; v[c4 * 4 + 1] = t.y;
        v[c4 * 4 + 2] = t.z; v[c4 * 4 + 3] = t.w;
    }
    float mx = -1e30f;
#pragma unroll
    for (int c = 0; c < Osz; ++c) {
        v[c] += d_b2p[c];
        mx = fmaxf(mx, v[c]);
    }
    float ssum = 0.f;
#pragma unroll
    for (int c = 0; c < Osz; ++c) { v[c] = expf(v[c] - mx); ssum += v[c]; }
    float inv = 1.f / ssum;
    float* orow = out + (size_t)r * Osz;
#pragma unroll
    for (int c = 0; c < Osz; c += 2) {
        float2 o; o.x = v[c] * inv; o.y = v[c + 1] * inv;
        *(float2*)(orow + c) = o;
    }
}

// ---------------- launcher ----------------
extern "C" void kernel_launch(void* const* d_in, const int* in_sizes, int n_in,
                              void* d_out, int out_size) {
    const int *x = 0, *w2c = 0;
    const float *wemb = 0, *cemb = 0, *convw = 0, *convb = 0;
    const float *w1 = 0, *b1 = 0, *w2 = 0, *b2 = 0;
    int seen50 = 0;
    for (int i = 0; i < n_in; ++i) {
        int s = in_sizes[i];
        if      (s == Bsz * Wsz)     x     = (const int*)d_in[i];
        else if (s == Vsz * Lsz)     w2c   = (const int*)d_in[i];
        else if (s == Vsz * Esz)     wemb  = (const float*)d_in[i];
        else if (s == Csz * Esz)     cemb  = (const float*)d_in[i];
        else if (s == Esz * Esz * 3) convw = (const float*)d_in[i];
        else if (s == Hsz * 250)     w1    = (const float*)d_in[i];
        else if (s == Hsz)           b1    = (const float*)d_in[i];
        else if (s == Osz * Hsz)     w2    = (const float*)d_in[i];
        else if (s == 50) {
            if (seen50++ == 0) convb = (const float*)d_in[i];
            else               b2    = (const float*)d_in[i];
        }
    }
    float* out = (float*)d_out;

    static bool attr_set = false;
    if (!attr_set) {
        cudaFuncSetAttribute(k_feat,  cudaFuncAttributeMaxDynamicSharedMemorySize, 80000);
        cudaFuncSetAttribute(k_fc1f,  cudaFuncAttributeMaxDynamicSharedMemorySize, FC1_SMEM);
        attr_set = true;
    }

    // launch 1: fused prep (zero + proj + w1 + w2)
    k_prep<<<6272, 256>>>(convw, cemb, w1, w2, b2);

    // launch 2: features -> chunked hi/lo (512 threads, prefetched gathers)
    size_t feat_smem = 19264 * sizeof(float);
    k_feat<<<NW / 64, 512, feat_smem>>>(x, w2c, wemb, convb);

    // launch 3: spacer (aligns fc1f with the ncu capture slot)
    k_noop<<<1, 32>>>();

    // launch 4: fused fc1 + fc2-partial (safe-early staging)
    k_fc1f<<<dim3(Hsz / 128, Bsz / 128), 256, FC1_SMEM>>>(b1);

    // launch 5: softmax
    k_smax<<<Bsz / 256, 256>>>(out);
}

// round 16
// speedup vs baseline: 1.5620x; 1.5620x over previous
#include <cuda_runtime.h>
#include <cuda_bf16.h>
#include <math.h>
#include <stdint.h>

// ---------------- problem constants ----------------
#define Bsz   16384
#define Wsz   5
#define Lsz   20
#define Esz   50
#define Vsz   100000
#define Csz   128
#define Hsz   4096
#define Osz   50
#define NW    (Bsz*Wsz)
#define KP2   256          // padded K (W*E = 250 -> 256)
// chunked hi/lo layout: sample = 8 chunks; chunk q = [hi k=32q..32q+31 | lo same] (64 bf16 = 128B)
#define SSTR  512          // bf16 elems per sample (256 hi + 256 lo)

// ---------------- device scratch ----------------
__device__ float d_proj[3 * Csz * Esz];
__device__ __align__(16) __nv_bfloat16 d_g1[Bsz * SSTR];      // 16.8 MB A hi/lo chunked
__device__ __align__(16) __nv_bfloat16 d_w1i[Hsz * SSTR];     // 4 MB   B hi/lo chunked
__device__ __align__(16) __nv_bfloat16 d_w2h[64 * Hsz];       // 512 KB
__device__ __align__(16) __nv_bfloat16 d_w2l[64 * Hsz];       // 512 KB
__device__ float d_b2p[64];
__device__ float d_logits[Bsz * 64];                          // 4 MB

// ---------------- helpers ----------------
__device__ __forceinline__ uint32_t smem_u32(const void* p) {
    uint32_t a;
    asm("{ .reg .u64 t; cvta.to.shared.u64 t, %1; cvt.u32.u64 %0, t; }" : "=r"(a) : "l"(p));
    return a;
}
#define SWZ128(o) ((o) ^ ((((uint32_t)(o)) >> 3) & 0x70))
__device__ __forceinline__ void cp16(uint32_t saddr, const void* g) {
    asm volatile("cp.async.cg.shared.global [%0], [%1], 16;" :: "r"(saddr), "l"(g));
}
#define CP_COMMIT() asm volatile("cp.async.commit_group;" ::: "memory")
#define CP_WAIT(n)  asm volatile("cp.async.wait_group %0;" :: "n"(n) : "memory")

__device__ __forceinline__ void ldm_x4(uint32_t* r, uint32_t saddr) {
    asm volatile("ldmatrix.sync.aligned.m8n8.x4.shared.b16 {%0,%1,%2,%3}, [%4];"
                 : "=r"(r[0]), "=r"(r[1]), "=r"(r[2]), "=r"(r[3]) : "r"(saddr));
}
__device__ __forceinline__ void mma16816(float* c, const uint32_t* a, uint32_t b0, uint32_t b1) {
    asm volatile("mma.sync.aligned.m16n8k16.row.col.f32.bf16.bf16.f32 "
                 "{%0,%1,%2,%3}, {%4,%5,%6,%7}, {%8,%9}, {%0,%1,%2,%3};"
                 : "+f"(c[0]), "+f"(c[1]), "+f"(c[2]), "+f"(c[3])
                 : "r"(a[0]), "r"(a[1]), "r"(a[2]), "r"(a[3]), "r"(b0), "r"(b1));
}

// ---------------- kernel 1: fused prep (zero logits, proj tables, w1 chunked, w2 split)
__global__ __launch_bounds__(256) void k_prep(const float* __restrict__ conv_w,
                                              const float* __restrict__ char_emb,
                                              const float* __restrict__ w1,
                                              const float* __restrict__ w2,
                                              const float* __restrict__ b2) {
    int blk = blockIdx.x;
    int tid = threadIdx.x;
    if (blk < 1024) {
        ((float4*)d_logits)[blk * 256 + tid] = make_float4(0.f, 0.f, 0.f, 0.f);
    } else if (blk < 1152) {
        if (tid >= 150) return;
        int k = tid / 50, e = tid % 50;
        int c = blk - 1024;
        float acc = 0.f;
#pragma unroll
        for (int i = 0; i < Esz; ++i)
            acc += conv_w[(e * Esz + i) * 3 + k] * char_emb[c * Esz + i];
        d_proj[k * (Csz * Esz) + c * Esz + e] = acc;
    } else if (blk < 5248) {
        int idx = (blk - 1152) * 256 + tid;            // < 4096*256
        int n = idx >> 8, k = idx & 255;
        float v = (k < 250) ? w1[n * 250 + k] : 0.f;
        __nv_bfloat16 hi = __float2bfloat16(v);
        __nv_bfloat16 lo = __float2bfloat16(v - __bfloat162float(hi));
        int q = k >> 5, p = k & 31;
        d_w1i[n * SSTR + q * 64 + p]      = hi;
        d_w1i[n * SSTR + q * 64 + 32 + p] = lo;
    } else {
        int idx = (blk - 5248) * 256 + tid;            // < 64*4096
        int o = idx >> 12;
        float v = (o < 50) ? w2[o * Hsz + (idx & 4095)] : 0.f;
        __nv_bfloat16 hi = __float2bfloat16(v);
        __nv_bfloat16 lo = __float2bfloat16(v - __bfloat162float(hi));
        d_w2h[idx] = hi;
        d_w2l[idx] = lo;
        if (idx < 64) d_b2p[idx] = (idx < 50) ? b2[idx] : 0.f;
    }
}

// ---------------- no-op spacer so k_fc1f lands in the ncu capture slot -------
__global__ void k_noop() {
    if (threadIdx.x > 1024) d_b2p[0] = 0.f;   // never true
}

// ---------------- kernel 3: features (warp-per-word, prefetched) -------------
__global__ __launch_bounds__(512) void k_feat(const int* __restrict__ x, const int* __restrict__ w2c,
                                              const float* __restrict__ wemb, const float* __restrict__ convb) {
    extern __shared__ float smf[];
    float* sp  = smf;            // 19200 floats: proj tables
    float* scb = smf + 19200;    // 64: conv bias

    int tid = threadIdx.x;
    for (int i = tid; i < 4800; i += 512)
        ((float4*)sp)[i] = ((const float4*)d_proj)[i];
    if (tid < 50) scb[tid] = convb[tid];
    __syncthreads();

    int lane = tid & 31, warp = tid >> 5;
    int base = blockIdx.x * 64 + warp * 4;
    bool act = lane < 25;
    int e2 = lane << 1;
    float2 cb = act ? *(const float2*)(scb + e2) : make_float2(0.f, 0.f);

    int xvs[4];
#pragma unroll
    for (int it = 0; it < 4; ++it) xvs[it] = x[base + it];
    int cidn = (lane < Lsz) ? w2c[xvs[0] * Lsz + lane] : 0;

#pragma unroll
    for (int it = 0; it < 4; ++it) {
        int xv = xvs[it];
        int cidreg = cidn;
        if (it < 3) cidn = (lane < Lsz) ? w2c[xvs[it + 1] * Lsz + lane] : 0;  // prefetch next
        float2 we = act ? *(const float2*)(wemb + xv * 50 + e2)              // early issue
                        : make_float2(0.f, 0.f);

        float m0 = -1e30f, m1 = -1e30f;
        int cp = 0;
        int cc = __shfl_sync(0xffffffffu, cidreg, 0);
#pragma unroll
        for (int l = 0; l < Lsz; ++l) {
            int cn = (l < Lsz - 1) ? __shfl_sync(0xffffffffu, cidreg, l + 1) : 0;
            if (act) {
                float2 s0 = *(const float2*)(sp + cp * 50 + e2);
                float2 s1 = *(const float2*)(sp + 6400 + cc * 50 + e2);
                float2 s2 = *(const float2*)(sp + 12800 + cn * 50 + e2);
                m0 = fmaxf(m0, s0.x + s1.x + s2.x);
                m1 = fmaxf(m1, s0.y + s1.y + s2.y);
            }
            cp = cc; cc = cn;
        }

        int b = (base + it) / Wsz, w = (base + it) - b * Wsz;
        if (act) {
            float v0 = we.x + m0 + cb.x;
            float v1 = we.y + m1 + cb.y;
            __nv_bfloat16 h0 = __float2bfloat16(v0);
            __nv_bfloat16 h1 = __float2bfloat16(v1);
            __nv_bfloat162 vh; vh.x = h0; vh.y = h1;
            __nv_bfloat162 vl;
            vl.x = __float2bfloat16(v0 - __bfloat162float(h0));
            vl.y = __float2bfloat16(v1 - __bfloat162float(h1));
            int col = w * 50 + e2;                       // even, pair stays in chunk
            int q = col >> 5, p = col & 31;
            int off = b * SSTR + q * 64 + p;
            *(__nv_bfloat162*)(d_g1 + off)      = vh;
            *(__nv_bfloat162*)(d_g1 + off + 32) = vl;
        } else if (lane < 28 && w == 0) {                // zero pads cols [250,256)
            int col = 250 + ((lane - 25) << 1);          // 250, 252, 254 (chunk 7)
            int q = col >> 5, p = col & 31;
            int off = b * SSTR + q * 64 + p;
            __nv_bfloat162 z2; z2.x = __float2bfloat16(0.f); z2.y = z2.x;
            *(__nv_bfloat162*)(d_g1 + off)      = z2;
            *(__nv_bfloat162*)(d_g1 + off + 32) = z2;
        }
    }
}

// ---------------- kernel 4: fused fc1 + fc2-partial, CTA 128x128 -------------
// EXACT revert to the R14 record version (459us total, fc1f 383us):
// 3-term split GEMM acc = Ah*Bh + Ah*Bl + Al*Bh. K=256 in 8 slabs of 32;
// 8 warps = 2(M)x4(N), warp 64x32. __launch_bounds__(256,2): 2 CTAs/SM.
// ONE sync/slab; stage(s+2) issued AFTER compute(s).
#define FC1_SMEM 98304
__global__ __launch_bounds__(256, 2) void k_fc1f(const float* __restrict__ b1) {
    extern __shared__ __align__(1024) char smc[];
    uint32_t sbase = smem_u32(smc);
    int tid = threadIdx.x;
    int lane = tid & 31, warp = tid >> 5;
    int wm = warp & 1, wn = warp >> 1;
    int bm = blockIdx.y << 7, bn = blockIdx.x << 7;

    float acc[4][4][4];
#pragma unroll
    for (int i = 0; i < 4; ++i)
#pragma unroll
        for (int j = 0; j < 4; ++j)
#pragma unroll
            for (int q = 0; q < 4; ++q) acc[i][j][q] = 0.f;

    const char* gA = (const char*)d_g1;
    const char* gB = (const char*)d_w1i;

    int lrow  = (lane & 7) + ((lane >> 3) & 1) * 8;
    int lchnk = (lane >> 4) << 4;
    uint32_t lsw = (uint32_t)((lane & 7) << 4);

    // stage slab s (chunk s = 128 bytes per sample row) into buffer buf
    auto stage = [&](int s, int buf) {
        uint32_t ab = sbase + buf * 32768;
        uint32_t bb = ab + 16384;
        int koff = s * 128;
#pragma unroll
        for (int i = 0; i < 4; ++i) {
            int idx = tid + (i << 8);
            int r = idx >> 3, c = (idx & 7) << 4;
            cp16(ab + SWZ128(r * 128 + c), gA + (size_t)(bm + r) * 1024 + koff + c);
        }
#pragma unroll
        for (int i = 0; i < 4; ++i) {
            int idx = tid + (i << 8);
            int r = idx >> 3, c = (idx & 7) << 4;
            cp16(bb + SWZ128(r * 128 + c), gB + (size_t)(bn + r) * 1024 + koff + c);
        }
    };

    // w2 epilogue slice (64 x 128 cols, hi+lo) -> [64K, 96K)
    auto stage_w2 = [&]() {
        const char* gW2h = (const char*)d_w2h;
        const char* gW2l = (const char*)d_w2l;
#pragma unroll
        for (int i = 0; i < 8; ++i) {
            int idx = tid + (i << 8);
            int hl = idx >> 10, rem = idx & 1023;
            int j = rem >> 9, rem2 = rem & 511;
            int o = rem2 >> 3, c = (rem2 & 7) << 4;
            const char* src = (hl ? gW2l : gW2h) + (size_t)o * 8192 + (size_t)(bn + (j << 6)) * 2 + c;
            cp16(sbase + 65536 + hl * 16384 + (j << 13) + SWZ128(o * 128 + c), src);
        }
    };

    stage(0, 0); CP_COMMIT();
    stage(1, 1); CP_COMMIT();

    for (int s = 0; s < 8; ++s) {
        int buf = s - (s / 3) * 3;                       // s % 3
        CP_WAIT(1);                                      // groups retire FIFO: slab s done
        __syncthreads();

        uint32_t ab = sbase + buf * 32768;
        uint32_t bb = ab + 16384;
        uint32_t arow[4], brow[2];
#pragma unroll
        for (int mt = 0; mt < 4; ++mt)
            arow[mt] = ab + (uint32_t)((wm << 6) + (mt << 4) + lrow) * 128;
#pragma unroll
        for (int np = 0; np < 2; ++np)
            brow[np] = bb + (uint32_t)((wn << 5) + (np << 4) + lrow) * 128;

#pragma unroll
        for (int kb = 0; kb < 2; ++kb) {                 // 2 k-steps of 16
            uint32_t khi = (uint32_t)(kb * 32 + lchnk) ^ lsw;
            uint32_t klo = (uint32_t)(64 + kb * 32 + lchnk) ^ lsw;

            // pass 1: ah·bh
            uint32_t ah[4][4], bh[2][4];
#pragma unroll
            for (int np = 0; np < 2; ++np) ldm_x4(bh[np], brow[np] + khi);
#pragma unroll
            for (int mt = 0; mt < 4; ++mt) ldm_x4(ah[mt], arow[mt] + khi);
#pragma unroll
            for (int mt = 0; mt < 4; ++mt)
#pragma unroll
                for (int np = 0; np < 2; ++np) {
                    mma16816(acc[mt][np * 2],     ah[mt], bh[np][0], bh[np][2]);
                    mma16816(acc[mt][np * 2 + 1], ah[mt], bh[np][1], bh[np][3]);
                }

            // pass 2: ah·bl
            uint32_t bl[2][4];
#pragma unroll
            for (int np = 0; np < 2; ++np) ldm_x4(bl[np], brow[np] + klo);
#pragma unroll
            for (int mt = 0; mt < 4; ++mt)
#pragma unroll
                for (int np = 0; np < 2; ++np) {
                    mma16816(acc[mt][np * 2],     ah[mt], bl[np][0], bl[np][2]);
                    mma16816(acc[mt][np * 2 + 1], ah[mt], bl[np][1], bl[np][3]);
                }

            // pass 3: al·bh (bh kept live)
            uint32_t al[4][4];
#pragma unroll
            for (int mt = 0; mt < 4; ++mt) ldm_x4(al[mt], arow[mt] + klo);
#pragma unroll
            for (int mt = 0; mt < 4; ++mt)
#pragma unroll
                for (int np = 0; np < 2; ++np) {
                    mma16816(acc[mt][np * 2],     al[mt], bh[np][0], bh[np][2]);
                    mma16816(acc[mt][np * 2 + 1], al[mt], bh[np][1], bh[np][3]);
                }
        }

        // stage ahead AFTER compute: buffer (s+2)%3 was last read in compute(s-1),
        // proven finished by this iteration's top __syncthreads.
        if (s + 2 < 8) {
            int nb = (s + 2) - ((s + 2) / 3) * 3;
            stage(s + 2, nb); CP_COMMIT();
        } else if (s == 6) {
            stage_w2(); CP_COMMIT();                     // buf-2 region free after compute(5)
        }
    }
    __syncthreads();   // all compute(7) reads done before h-store reuses bufs 0/1

    // ---- epilogue phase 2: tanh + split, h tile -> smem [0, 64K) ----
    int r0 = lane >> 2, c0 = (lane & 3) << 1;
#pragma unroll
    for (int mt = 0; mt < 4; ++mt) {
#pragma unroll
        for (int nt = 0; nt < 4; ++nt) {
            int col = (wn << 5) + (nt << 3) + c0;       // 0..127 local
            float bias0 = b1[bn + col], bias1 = b1[bn + col + 1];
            int slab = col >> 6, inner = col & 63;
#pragma unroll
            for (int half = 0; half < 2; ++half) {
                int rowl = (wm << 6) + (mt << 4) + r0 + (half << 3);
                float t0 = tanhf(acc[mt][nt][half * 2 + 0] + bias0);
                float t1 = tanhf(acc[mt][nt][half * 2 + 1] + bias1);
                __nv_bfloat16 h0 = __float2bfloat16(t0);
                __nv_bfloat16 h1 = __float2bfloat16(t1);
                __nv_bfloat162 vh; vh.x = h0; vh.y = h1;
                __nv_bfloat162 vl;
                vl.x = __float2bfloat16(t0 - __bfloat162float(h0));
                vl.y = __float2bfloat16(t1 - __bfloat162float(h1));
                uint32_t off = SWZ128((uint32_t)rowl * 128 + inner * 2);
                *(__nv_bfloat162*)(smc + (slab << 14) + off)         = vh;
                *(__nv_bfloat162*)(smc + 32768 + (slab << 14) + off) = vl;
            }
        }
    }
    CP_WAIT(0);
    __syncthreads();

    // ---- epilogue phase 3: mini GEMM, logits partial [128x64], K=128 ----
    float a2[4][2][4];
#pragma unroll
    for (int i = 0; i < 4; ++i)
#pragma unroll
        for (int j = 0; j < 2; ++j)
#pragma unroll
            for (int q = 0; q < 4; ++q) a2[i][j][q] = 0.f;

#pragma unroll
    for (int slab = 0; slab < 2; ++slab) {
        uint32_t ahb = sbase + (slab << 14);
        uint32_t alb = ahb + 32768;
        uint32_t bhb = sbase + 65536 + (slab << 13);
        uint32_t blb = bhb + 16384;
        uint32_t brw = (uint32_t)((wn << 4) + lrow) * 128;
#pragma unroll
        for (int kb = 0; kb < 4; ++kb) {
            uint32_t koffb = (uint32_t)(kb * 32 + lchnk) ^ lsw;
            uint32_t bh[4], bl[4];
            ldm_x4(bh, bhb + brw + koffb);
            ldm_x4(bl, blb + brw + koffb);
#pragma unroll
            for (int mt = 0; mt < 4; ++mt) {
                uint32_t arw = (uint32_t)((wm << 6) + (mt << 4) + lrow) * 128;
                uint32_t ah[4], al[4];
                ldm_x4(ah, ahb + arw + koffb);
                ldm_x4(al, alb + arw + koffb);
                mma16816(a2[mt][0], ah, bh[0], bh[2]);
                mma16816(a2[mt][1], ah, bh[1], bh[3]);
                mma16816(a2[mt][0], ah, bl[0], bl[2]);
                mma16816(a2[mt][1], ah, bl[1], bl[3]);
                mma16816(a2[mt][0], al, bh[0], bh[2]);
                mma16816(a2[mt][1], al, bh[1], bh[3]);
            }
        }
    }

    // ---- epilogue phase 4: atomic accumulate ----
#pragma unroll
    for (int mt = 0; mt < 4; ++mt) {
#pragma unroll
        for (int nt = 0; nt < 2; ++nt) {
            int colg = (wn << 4) + (nt << 3) + c0;
#pragma unroll
            for (int half = 0; half < 2; ++half) {
                int rowg = bm + (wm << 6) + (mt << 4) + r0 + (half << 3);
                atomicAdd(&d_logits[rowg * 64 + colg],     a2[mt][nt][half * 2 + 0]);
                atomicAdd(&d_logits[rowg * 64 + colg + 1], a2[mt][nt][half * 2 + 1]);
            }
        }
    }
}

// ---------------- kernel 5: softmax over logits (vectorized loads) ----------
__global__ __launch_bounds__(256) void k_smax(float* __restrict__ out) {
    int r = blockIdx.x * 256 + threadIdx.x;
    const float4* lr4 = (const float4*)(d_logits + r * 64);
    float v[52];
#pragma unroll
    for (int c4 = 0; c4 < 13; ++c4) {                    // 52 >= 50 cols
        float4 t = lr4[c4];
        v[c4 * 4 + 0] = t.x; v[c4 * 4 + 1] = t.y;
        v[c4 * 4 + 2] = t.z; v[c4 * 4 + 3] = t.w;
    }
    float mx = -1e30f;
#pragma unroll
    for (int c = 0; c < Osz; ++c) {
        v[c] += d_b2p[c];
        mx = fmaxf(mx, v[c]);
    }
    float ssum = 0.f;
#pragma unroll
    for (int c = 0; c < Osz; ++c) { v[c] = expf(v[c] - mx); ssum += v[c]; }
    float inv = 1.f / ssum;
    float* orow = out + (size_t)r * Osz;
#pragma unroll
    for (int c = 0; c < Osz; c += 2) {
        float2 o; o.x = v[c] * inv; o.y = v[c + 1] * inv;
        *(float2*)(orow + c) = o;
    }
}

// ---------------- launcher ----------------
extern "C" void kernel_launch(void* const* d_in, const int* in_sizes, int n_in,
                              void* d_out, int out_size) {
    const int *x = 0, *w2c = 0;
    const float *wemb = 0, *cemb = 0, *convw = 0, *convb = 0;
    const float *w1 = 0, *b1 = 0, *w2 = 0, *b2 = 0;
    int seen50 = 0;
    for (int i = 0; i < n_in; ++i) {
        int s = in_sizes[i];
        if      (s == Bsz * Wsz)     x     = (const int*)d_in[i];
        else if (s == Vsz * Lsz)     w2c   = (const int*)d_in[i];
        else if (s == Vsz * Esz)     wemb  = (const float*)d_in[i];
        else if (s == Csz * Esz)     cemb  = (const float*)d_in[i];
        else if (s == Esz * Esz * 3) convw = (const float*)d_in[i];
        else if (s == Hsz * 250)     w1    = (const float*)d_in[i];
        else if (s == Hsz)           b1    = (const float*)d_in[i];
        else if (s == Osz * Hsz)     w2    = (const float*)d_in[i];
        else if (s == 50) {
            if (seen50++ == 0) convb = (const float*)d_in[i];
            else               b2    = (const float*)d_in[i];
        }
    }
    float* out = (float*)d_out;

    static bool attr_set = false;
    if (!attr_set) {
        cudaFuncSetAttribute(k_feat,  cudaFuncAttributeMaxDynamicSharedMemorySize, 80000);
        cudaFuncSetAttribute(k_fc1f,  cudaFuncAttributeMaxDynamicSharedMemorySize, FC1_SMEM);
        attr_set = true;
    }

    // launch 1: fused prep (zero + proj + w1 + w2)
    k_prep<<<6272, 256>>>(convw, cemb, w1, w2, b2);

    // launch 2: features -> chunked hi/lo (512 threads, prefetched gathers)
    size_t feat_smem = 19264 * sizeof(float);
    k_feat<<<NW / 64, 512, feat_smem>>>(x, w2c, wemb, convb);

    // launch 3: spacer (aligns fc1f with the ncu capture slot)
    k_noop<<<1, 32>>>();

    // launch 4: fused fc1 + fc2-partial (R14 record version, exact)
    k_fc1f<<<dim3(Hsz / 128, Bsz / 128), 256, FC1_SMEM>>>(b1);

    // launch 5: softmax
    k_smax<<<Bsz / 256, 256>>>(out);
}

// round 17
// speedup vs baseline: 1.6589x; 1.0621x over previous
#include <cuda_runtime.h>
#include <cuda_bf16.h>
#include <math.h>
#include <stdint.h>

// ---------------- problem constants ----------------
#define Bsz   16384
#define Wsz   5
#define Lsz   20
#define Esz   50
#define Vsz   100000
#define Csz   128
#define Hsz   4096
#define Osz   50
#define NW    (Bsz*Wsz)
#define KP2   256          // padded K (W*E = 250 -> 256)
// chunked hi/lo layout: sample = 8 chunks; chunk q = [hi k=32q..32q+31 | lo same] (64 bf16 = 128B)
#define SSTR  512          // bf16 elems per sample (256 hi + 256 lo)

// ---------------- device scratch ----------------
__device__ float d_proj[3 * Csz * Esz];
__device__ __align__(16) __nv_bfloat16 d_g1[Bsz * SSTR];      // 16.8 MB A hi/lo chunked
__device__ __align__(16) __nv_bfloat16 d_w1i[Hsz * SSTR];     // 4 MB   B hi/lo chunked
__device__ __align__(16) __nv_bfloat16 d_w2h[64 * Hsz];       // 512 KB
__device__ __align__(16) __nv_bfloat16 d_w2l[64 * Hsz];       // 512 KB
__device__ float d_b2p[64];
__device__ float d_logits[Bsz * 64];                          // 4 MB

// ---------------- helpers ----------------
__device__ __forceinline__ uint32_t smem_u32(const void* p) {
    uint32_t a;
    asm("{ .reg .u64 t; cvta.to.shared.u64 t, %1; cvt.u32.u64 %0, t; }" : "=r"(a) : "l"(p));
    return a;
}
#define SWZ128(o) ((o) ^ ((((uint32_t)(o)) >> 3) & 0x70))
__device__ __forceinline__ void cp16(uint32_t saddr, const void* g) {
    asm volatile("cp.async.cg.shared.global [%0], [%1], 16;" :: "r"(saddr), "l"(g));
}
#define CP_COMMIT() asm volatile("cp.async.commit_group;" ::: "memory")
#define CP_WAIT(n)  asm volatile("cp.async.wait_group %0;" :: "n"(n) : "memory")

__device__ __forceinline__ void ldm_x4(uint32_t* r, uint32_t saddr) {
    asm volatile("ldmatrix.sync.aligned.m8n8.x4.shared.b16 {%0,%1,%2,%3}, [%4];"
                 : "=r"(r[0]), "=r"(r[1]), "=r"(r[2]), "=r"(r[3]) : "r"(saddr));
}
__device__ __forceinline__ void mma16816(float* c, const uint32_t* a, uint32_t b0, uint32_t b1) {
    asm volatile("mma.sync.aligned.m16n8k16.row.col.f32.bf16.bf16.f32 "
                 "{%0,%1,%2,%3}, {%4,%5,%6,%7}, {%8,%9}, {%0,%1,%2,%3};"
                 : "+f"(c[0]), "+f"(c[1]), "+f"(c[2]), "+f"(c[3])
                 : "r"(a[0]), "r"(a[1]), "r"(a[2]), "r"(a[3]), "r"(b0), "r"(b1));
}
// single-MUFU tanh (sm_75+ baseline PTX; |err| <= ~4.9e-4 abs)
__device__ __forceinline__ float tanh_fast(float x) {
    float y;
    asm("tanh.approx.f32 %0, %1;" : "=f"(y) : "f"(x));
    return y;
}
// pack {lo=a, hi=b} into bf16x2 (1 instr)
__device__ __forceinline__ uint32_t pack_bf16x2(float a, float b) {
    uint32_t d;
    asm("cvt.rn.bf16x2.f32 %0, %1, %2;" : "=r"(d) : "f"(b), "f"(a));
    return d;
}

// ---------------- kernel 1: fused prep (zero logits, proj tables, w1 chunked, w2 split)
__global__ __launch_bounds__(256) void k_prep(const float* __restrict__ conv_w,
                                              const float* __restrict__ char_emb,
                                              const float* __restrict__ w1,
                                              const float* __restrict__ w2,
                                              const float* __restrict__ b2) {
    int blk = blockIdx.x;
    int tid = threadIdx.x;
    if (blk < 1024) {
        ((float4*)d_logits)[blk * 256 + tid] = make_float4(0.f, 0.f, 0.f, 0.f);
    } else if (blk < 1152) {
        if (tid >= 150) return;
        int k = tid / 50, e = tid % 50;
        int c = blk - 1024;
        float acc = 0.f;
#pragma unroll
        for (int i = 0; i < Esz; ++i)
            acc += conv_w[(e * Esz + i) * 3 + k] * char_emb[c * Esz + i];
        d_proj[k * (Csz * Esz) + c * Esz + e] = acc;
    } else if (blk < 5248) {
        int idx = (blk - 1152) * 256 + tid;            // < 4096*256
        int n = idx >> 8, k = idx & 255;
        float v = (k < 250) ? w1[n * 250 + k] : 0.f;
        __nv_bfloat16 hi = __float2bfloat16(v);
        __nv_bfloat16 lo = __float2bfloat16(v - __bfloat162float(hi));
        int q = k >> 5, p = k & 31;
        d_w1i[n * SSTR + q * 64 + p]      = hi;
        d_w1i[n * SSTR + q * 64 + 32 + p] = lo;
    } else {
        int idx = (blk - 5248) * 256 + tid;            // < 64*4096
        int o = idx >> 12;
        float v = (o < 50) ? w2[o * Hsz + (idx & 4095)] : 0.f;
        __nv_bfloat16 hi = __float2bfloat16(v);
        __nv_bfloat16 lo = __float2bfloat16(v - __bfloat162float(hi));
        d_w2h[idx] = hi;
        d_w2l[idx] = lo;
        if (idx < 64) d_b2p[idx] = (idx < 50) ? b2[idx] : 0.f;
    }
}

// ---------------- no-op spacer so k_fc1f lands in the ncu capture slot -------
__global__ void k_noop() {
    if (threadIdx.x > 1024) d_b2p[0] = 0.f;   // never true
}

// ---------------- kernel 3: features (warp-per-word, prefetched) -------------
__global__ __launch_bounds__(512) void k_feat(const int* __restrict__ x, const int* __restrict__ w2c,
                                              const float* __restrict__ wemb, const float* __restrict__ convb) {
    extern __shared__ float smf[];
    float* sp  = smf;            // 19200 floats: proj tables
    float* scb = smf + 19200;    // 64: conv bias

    int tid = threadIdx.x;
    for (int i = tid; i < 4800; i += 512)
        ((float4*)sp)[i] = ((const float4*)d_proj)[i];
    if (tid < 50) scb[tid] = convb[tid];
    __syncthreads();

    int lane = tid & 31, warp = tid >> 5;
    int base = blockIdx.x * 64 + warp * 4;
    bool act = lane < 25;
    int e2 = lane << 1;
    float2 cb = act ? *(const float2*)(scb + e2) : make_float2(0.f, 0.f);

    int xvs[4];
#pragma unroll
    for (int it = 0; it < 4; ++it) xvs[it] = x[base + it];
    int cidn = (lane < Lsz) ? w2c[xvs[0] * Lsz + lane] : 0;

#pragma unroll
    for (int it = 0; it < 4; ++it) {
        int xv = xvs[it];
        int cidreg = cidn;
        if (it < 3) cidn = (lane < Lsz) ? w2c[xvs[it + 1] * Lsz + lane] : 0;  // prefetch next
        float2 we = act ? *(const float2*)(wemb + xv * 50 + e2)              // early issue
                        : make_float2(0.f, 0.f);

        float m0 = -1e30f, m1 = -1e30f;
        int cp = 0;
        int cc = __shfl_sync(0xffffffffu, cidreg, 0);
#pragma unroll
        for (int l = 0; l < Lsz; ++l) {
            int cn = (l < Lsz - 1) ? __shfl_sync(0xffffffffu, cidreg, l + 1) : 0;
            if (act) {
                float2 s0 = *(const float2*)(sp + cp * 50 + e2);
                float2 s1 = *(const float2*)(sp + 6400 + cc * 50 + e2);
                float2 s2 = *(const float2*)(sp + 12800 + cn * 50 + e2);
                m0 = fmaxf(m0, s0.x + s1.x + s2.x);
                m1 = fmaxf(m1, s0.y + s1.y + s2.y);
            }
            cp = cc; cc = cn;
        }

        int b = (base + it) / Wsz, w = (base + it) - b * Wsz;
        if (act) {
            float v0 = we.x + m0 + cb.x;
            float v1 = we.y + m1 + cb.y;
            __nv_bfloat16 h0 = __float2bfloat16(v0);
            __nv_bfloat16 h1 = __float2bfloat16(v1);
            __nv_bfloat162 vh; vh.x = h0; vh.y = h1;
            __nv_bfloat162 vl;
            vl.x = __float2bfloat16(v0 - __bfloat162float(h0));
            vl.y = __float2bfloat16(v1 - __bfloat162float(h1));
            int col = w * 50 + e2;                       // even, pair stays in chunk
            int q = col >> 5, p = col & 31;
            int off = b * SSTR + q * 64 + p;
            *(__nv_bfloat162*)(d_g1 + off)      = vh;
            *(__nv_bfloat162*)(d_g1 + off + 32) = vl;
        } else if (lane < 28 && w == 0) {                // zero pads cols [250,256)
            int col = 250 + ((lane - 25) << 1);          // 250, 252, 254 (chunk 7)
            int q = col >> 5, p = col & 31;
            int off = b * SSTR + q * 64 + p;
            __nv_bfloat162 z2; z2.x = __float2bfloat16(0.f); z2.y = z2.x;
            *(__nv_bfloat162*)(d_g1 + off)      = z2;
            *(__nv_bfloat162*)(d_g1 + off + 32) = z2;
        }
    }
}

// ---------------- kernel 4: fused fc1 + fc2-partial, CTA 128x128 -------------
// Mainloop identical to the R14/R16 record version. Epilogue scalar cost cut:
// tanh.approx (1 MUFU vs ~20 instrs) + cvt.rn.bf16x2 packing (the epilogue was
// ~100us of scalar work per the R16 instruction accounting).
#define FC1_SMEM 98304
__global__ __launch_bounds__(256, 2) void k_fc1f(const float* __restrict__ b1) {
    extern __shared__ __align__(1024) char smc[];
    uint32_t sbase = smem_u32(smc);
    int tid = threadIdx.x;
    int lane = tid & 31, warp = tid >> 5;
    int wm = warp & 1, wn = warp >> 1;
    int bm = blockIdx.y << 7, bn = blockIdx.x << 7;

    float acc[4][4][4];
#pragma unroll
    for (int i = 0; i < 4; ++i)
#pragma unroll
        for (int j = 0; j < 4; ++j)
#pragma unroll
            for (int q = 0; q < 4; ++q) acc[i][j][q] = 0.f;

    const char* gA = (const char*)d_g1;
    const char* gB = (const char*)d_w1i;

    int lrow  = (lane & 7) + ((lane >> 3) & 1) * 8;
    int lchnk = (lane >> 4) << 4;
    uint32_t lsw = (uint32_t)((lane & 7) << 4);

    // stage slab s (chunk s = 128 bytes per sample row) into buffer buf
    auto stage = [&](int s, int buf) {
        uint32_t ab = sbase + buf * 32768;
        uint32_t bb = ab + 16384;
        int koff = s * 128;
#pragma unroll
        for (int i = 0; i < 4; ++i) {
            int idx = tid + (i << 8);
            int r = idx >> 3, c = (idx & 7) << 4;
            cp16(ab + SWZ128(r * 128 + c), gA + (size_t)(bm + r) * 1024 + koff + c);
        }
#pragma unroll
        for (int i = 0; i < 4; ++i) {
            int idx = tid + (i << 8);
            int r = idx >> 3, c = (idx & 7) << 4;
            cp16(bb + SWZ128(r * 128 + c), gB + (size_t)(bn + r) * 1024 + koff + c);
        }
    };

    // w2 epilogue slice (64 x 128 cols, hi+lo) -> [64K, 96K)
    auto stage_w2 = [&]() {
        const char* gW2h = (const char*)d_w2h;
        const char* gW2l = (const char*)d_w2l;
#pragma unroll
        for (int i = 0; i < 8; ++i) {
            int idx = tid + (i << 8);
            int hl = idx >> 10, rem = idx & 1023;
            int j = rem >> 9, rem2 = rem & 511;
            int o = rem2 >> 3, c = (rem2 & 7) << 4;
            const char* src = (hl ? gW2l : gW2h) + (size_t)o * 8192 + (size_t)(bn + (j << 6)) * 2 + c;
            cp16(sbase + 65536 + hl * 16384 + (j << 13) + SWZ128(o * 128 + c), src);
        }
    };

    stage(0, 0); CP_COMMIT();
    stage(1, 1); CP_COMMIT();

    for (int s = 0; s < 8; ++s) {
        int buf = s - (s / 3) * 3;                       // s % 3
        CP_WAIT(1);                                      // groups retire FIFO: slab s done
        __syncthreads();

        uint32_t ab = sbase + buf * 32768;
        uint32_t bb = ab + 16384;
        uint32_t arow[4], brow[2];
#pragma unroll
        for (int mt = 0; mt < 4; ++mt)
            arow[mt] = ab + (uint32_t)((wm << 6) + (mt << 4) + lrow) * 128;
#pragma unroll
        for (int np = 0; np < 2; ++np)
            brow[np] = bb + (uint32_t)((wn << 5) + (np << 4) + lrow) * 128;

#pragma unroll
        for (int kb = 0; kb < 2; ++kb) {                 // 2 k-steps of 16
            uint32_t khi = (uint32_t)(kb * 32 + lchnk) ^ lsw;
            uint32_t klo = (uint32_t)(64 + kb * 32 + lchnk) ^ lsw;

            // pass 1: ah·bh
            uint32_t ah[4][4], bh[2][4];
#pragma unroll
            for (int np = 0; np < 2; ++np) ldm_x4(bh[np], brow[np] + khi);
#pragma unroll
            for (int mt = 0; mt < 4; ++mt) ldm_x4(ah[mt], arow[mt] + khi);
#pragma unroll
            for (int mt = 0; mt < 4; ++mt)
#pragma unroll
                for (int np = 0; np < 2; ++np) {
                    mma16816(acc[mt][np * 2],     ah[mt], bh[np][0], bh[np][2]);
                    mma16816(acc[mt][np * 2 + 1], ah[mt], bh[np][1], bh[np][3]);
                }

            // pass 2: ah·bl
            uint32_t bl[2][4];
#pragma unroll
            for (int np = 0; np < 2; ++np) ldm_x4(bl[np], brow[np] + klo);
#pragma unroll
            for (int mt = 0; mt < 4; ++mt)
#pragma unroll
                for (int np = 0; np < 2; ++np) {
                    mma16816(acc[mt][np * 2],     ah[mt], bl[np][0], bl[np][2]);
                    mma16816(acc[mt][np * 2 + 1], ah[mt], bl[np][1], bl[np][3]);
                }

            // pass 3: al·bh (bh kept live)
            uint32_t al[4][4];
#pragma unroll
            for (int mt = 0; mt < 4; ++mt) ldm_x4(al[mt], arow[mt] + klo);
#pragma unroll
            for (int mt = 0; mt < 4; ++mt)
#pragma unroll
                for (int np = 0; np < 2; ++np) {
                    mma16816(acc[mt][np * 2],     al[mt], bh[np][0], bh[np][2]);
                    mma16816(acc[mt][np * 2 + 1], al[mt], bh[np][1], bh[np][3]);
                }
        }

        // stage ahead AFTER compute (R14 ordering)
        if (s + 2 < 8) {
            int nb = (s + 2) - ((s + 2) / 3) * 3;
            stage(s + 2, nb); CP_COMMIT();
        } else if (s == 6) {
            stage_w2(); CP_COMMIT();                     // buf-2 region free after compute(5)
        }
    }
    __syncthreads();   // all compute(7) reads done before h-store reuses bufs 0/1

    // ---- epilogue phase 2: fast tanh + packed split, h tile -> smem [0, 64K) ----
    int r0 = lane >> 2, c0 = (lane & 3) << 1;
#pragma unroll
    for (int mt = 0; mt < 4; ++mt) {
#pragma unroll
        for (int nt = 0; nt < 4; ++nt) {
            int col = (wn << 5) + (nt << 3) + c0;       // 0..127 local
            float bias0 = b1[bn + col], bias1 = b1[bn + col + 1];
            int slab = col >> 6, inner = col & 63;
#pragma unroll
            for (int half = 0; half < 2; ++half) {
                int rowl = (wm << 6) + (mt << 4) + r0 + (half << 3);
                float t0 = tanh_fast(acc[mt][nt][half * 2 + 0] + bias0);
                float t1 = tanh_fast(acc[mt][nt][half * 2 + 1] + bias1);
                uint32_t vh = pack_bf16x2(t0, t1);       // {lo=t0, hi=t1}
                float h0f = __uint_as_float(vh << 16);
                float h1f = __uint_as_float(vh & 0xffff0000u);
                uint32_t vl = pack_bf16x2(t0 - h0f, t1 - h1f);
                uint32_t off = SWZ128((uint32_t)rowl * 128 + inner * 2);
                *(uint32_t*)(smc + (slab << 14) + off)         = vh;
                *(uint32_t*)(smc + 32768 + (slab << 14) + off) = vl;
            }
        }
    }
    CP_WAIT(0);
    __syncthreads();

    // ---- epilogue phase 3: mini GEMM, logits partial [128x64], K=128 ----
    float a2[4][2][4];
#pragma unroll
    for (int i = 0; i < 4; ++i)
#pragma unroll
        for (int j = 0; j < 2; ++j)
#pragma unroll
            for (int q = 0; q < 4; ++q) a2[i][j][q] = 0.f;

#pragma unroll
    for (int slab = 0; slab < 2; ++slab) {
        uint32_t ahb = sbase + (slab << 14);
        uint32_t alb = ahb + 32768;
        uint32_t bhb = sbase + 65536 + (slab << 13);
        uint32_t blb = bhb + 16384;
        uint32_t brw = (uint32_t)((wn << 4) + lrow) * 128;
#pragma unroll
        for (int kb = 0; kb < 4; ++kb) {
            uint32_t koffb = (uint32_t)(kb * 32 + lchnk) ^ lsw;
            uint32_t bh[4], bl[4];
            ldm_x4(bh, bhb + brw + koffb);
            ldm_x4(bl, blb + brw + koffb);
#pragma unroll
            for (int mt = 0; mt < 4; ++mt) {
                uint32_t arw = (uint32_t)((wm << 6) + (mt << 4) + lrow) * 128;
                uint32_t ah[4], al[4];
                ldm_x4(ah, ahb + arw + koffb);
                ldm_x4(al, alb + arw + koffb);
                mma16816(a2[mt][0], ah, bh[0], bh[2]);
                mma16816(a2[mt][1], ah, bh[1], bh[3]);
                mma16816(a2[mt][0], ah, bl[0], bl[2]);
                mma16816(a2[mt][1], ah, bl[1], bl[3]);
                mma16816(a2[mt][0], al, bh[0], bh[2]);
                mma16816(a2[mt][1], al, bh[1], bh[3]);
            }
        }
    }

    // ---- epilogue phase 4: atomic accumulate ----
#pragma unroll
    for (int mt = 0; mt < 4; ++mt) {
#pragma unroll
        for (int nt = 0; nt < 2; ++nt) {
            int colg = (wn << 4) + (nt << 3) + c0;
#pragma unroll
            for (int half = 0; half < 2; ++half) {
                int rowg = bm + (wm << 6) + (mt << 4) + r0 + (half << 3);
                atomicAdd(&d_logits[rowg * 64 + colg],     a2[mt][nt][half * 2 + 0]);
                atomicAdd(&d_logits[rowg * 64 + colg + 1], a2[mt][nt][half * 2 + 1]);
            }
        }
    }
}

// ---------------- kernel 5: softmax over logits (vectorized loads) ----------
__global__ __launch_bounds__(256) void k_smax(float* __restrict__ out) {
    int r = blockIdx.x * 256 + threadIdx.x;
    const float4* lr4 = (const float4*)(d_logits + r * 64);
    float v[52];
#pragma unroll
    for (int c4 = 0; c4 < 13; ++c4) {                    // 52 >= 50 cols
        float4 t = lr4[c4];
        v[c4 * 4 + 0] = t.x; v[c4 * 4 + 1] = t.y;
        v[c4 * 4 + 2] = t.z; v[c4 * 4 + 3] = t.w;
    }
    float mx = -1e30f;
#pragma unroll
    for (int c = 0; c < Osz; ++c) {
        v[c] += d_b2p[c];
        mx = fmaxf(mx, v[c]);
    }
    float ssum = 0.f;
#pragma unroll
    for (int c = 0; c < Osz; ++c) { v[c] = expf(v[c] - mx); ssum += v[c]; }
    float inv = 1.f / ssum;
    float* orow = out + (size_t)r * Osz;
#pragma unroll
    for (int c = 0; c < Osz; c += 2) {
        float2 o; o.x = v[c] * inv; o.y = v[c + 1] * inv;
        *(float2*)(orow + c) = o;
    }
}

// ---------------- launcher ----------------
extern "C" void kernel_launch(void* const* d_in, const int* in_sizes, int n_in,
                              void* d_out, int out_size) {
    const int *x = 0, *w2c = 0;
    const float *wemb = 0, *cemb = 0, *convw = 0, *convb = 0;
    const float *w1 = 0, *b1 = 0, *w2 = 0, *b2 = 0;
    int seen50 = 0;
    for (int i = 0; i < n_in; ++i) {
        int s = in_sizes[i];
        if      (s == Bsz * Wsz)     x     = (const int*)d_in[i];
        else if (s == Vsz * Lsz)     w2c   = (const int*)d_in[i];
        else if (s == Vsz * Esz)     wemb  = (const float*)d_in[i];
        else if (s == Csz * Esz)     cemb  = (const float*)d_in[i];
        else if (s == Esz * Esz * 3) convw = (const float*)d_in[i];
        else if (s == Hsz * 250)     w1    = (const float*)d_in[i];
        else if (s == Hsz)           b1    = (const float*)d_in[i];
        else if (s == Osz * Hsz)     w2    = (const float*)d_in[i];
        else if (s == 50) {
            if (seen50++ == 0) convb = (const float*)d_in[i];
            else               b2    = (const float*)d_in[i];
        }
    }
    float* out = (float*)d_out;

    static bool attr_set = false;
    if (!attr_set) {
        cudaFuncSetAttribute(k_feat,  cudaFuncAttributeMaxDynamicSharedMemorySize, 80000);
        cudaFuncSetAttribute(k_fc1f,  cudaFuncAttributeMaxDynamicSharedMemorySize, FC1_SMEM);
        attr_set = true;
    }

    // launch 1: fused prep (zero + proj + w1 + w2)
    k_prep<<<6272, 256>>>(convw, cemb, w1, w2, b2);

    // launch 2: features -> chunked hi/lo (512 threads, prefetched gathers)
    size_t feat_smem = 19264 * sizeof(float);
    k_feat<<<NW / 64, 512, feat_smem>>>(x, w2c, wemb, convb);

    // launch 3: spacer (aligns fc1f with the ncu capture slot)
    k_noop<<<1, 32>>>();

    // launch 4: fused fc1 + fc2-partial (fast-tanh epilogue)
    k_fc1f<<<dim3(Hsz / 128, Bsz / 128), 256, FC1_SMEM>>>(b1);

    // launch 5: softmax
    k_smax<<<Bsz / 256, 256>>>(out);
}